// round 7
// baseline (speedup 1.0000x reference)
#include <cuda_runtime.h>
#include <math.h>

#define NN   500
#define DEG  16
#define BB   8
#define TT   12
#define HH   64
#define FF   32
#define EE   (NN*DEG)      // 8000
#define BT   (BB*TT)       // 96
#define M1C  16
#define M2C  2
#define DOUT (2*HH*HH)     // 8192
#define PLANE (BT*HH)      // 6144

#define ROWS_PB 48                     // bt rows per K2 block (half node)
#define K2_SMEM_S (ROWS_PB*HH)         // 3072 floats
#define K2_SMEM_W (HH*256)             // 16384 floats (main, col-permuted)
#define K2_SMEM_WZ (HH*128)            // 8192 floats (bias planes)
#define K2_SMEM_BYTES ((K2_SMEM_S + K2_SMEM_W + K2_SMEM_WZ)*4)   // 110592

// Static scratch (allocation-free)
__device__ int   g_bias_nz;
__device__ float g_c[EE*2];                  // per-edge (c0,c1)
__device__ float g_A[(size_t)NN*PLANE*2];    // src-side planes interleaved (x0,x1)
__device__ float g_B[(size_t)NN*PLANE*2];    // dst-side planes interleaved (y0,y1)
__device__ float g_Az[(size_t)NN*PLANE];     // src bias plane (only if b3 != 0)
__device__ float g_Bz[(size_t)NN*PLANE];     // dst bias plane

typedef unsigned long long ull;

__device__ __forceinline__ ull dup2(float x) {
    ull r;
    asm("mov.b64 %0, {%1, %1};" : "=l"(r) : "r"(__float_as_uint(x)));
    return r;
}
__device__ __forceinline__ void ffma2(ull& d, ull a, ull b) {
    asm("fma.rn.f32x2 %0, %1, %2, %3;" : "=l"(d) : "l"(a), "l"(b), "l"(d));
}
__device__ __forceinline__ void unpk2(ull v, float& lo, float& hi) {
    unsigned ulo, uhi;
    asm("mov.b64 {%0, %1}, %2;" : "=r"(ulo), "=r"(uhi) : "l"(v));
    lo = __uint_as_float(ulo); hi = __uint_as_float(uhi);
}
__device__ __forceinline__ float sigmoidf_(float x) { return 1.0f / (1.0f + __expf(-x)); }

// ---------------------------------------------------------------------------
// K2: grid = 2N blocks (node, bt-half). Each block computes
//   s_half[48,64] @ Wfull[64,256]  (cols permuted to (h,m)-interleaved layout:
//   cols 0..127 -> g_A, 128..255 -> g_B), plus a cold 128-col bias pass.
// Thread tile: 6 rows x 8 cols; warp-uniform s broadcasts; FFMA2 throughout.
// half==0 blocks also run the per-edge hypernetwork (16 edges x 16 units).
// ---------------------------------------------------------------------------
__global__ void __launch_bounds__(256) k2_precompute(
        const float* __restrict__ state,
        const float* __restrict__ feature,
        const float* __restrict__ dist,
        const float* __restrict__ W1,
        const float* __restrict__ b1,
        const float* __restrict__ W2,
        const float* __restrict__ b2,
        const float* __restrict__ W3,
        const float* __restrict__ b3,
        const int*   __restrict__ src,
        const int*   __restrict__ dst) {
    extern __shared__ float sm[];
    float* s_sm  = sm;                         // [48][64]
    float* w_sm  = sm + K2_SMEM_S;             // [64][256] permuted
    float* wz_sm = w_sm + K2_SMEM_W;           // [64][128] bias planes

    int bid  = blockIdx.x;
    int n    = bid >> 1;
    int half = bid & 1;
    int tid  = threadIdx.x;

    // ---- bias-nonzero scan (b3 = 32KB, L2-resident) ----
    int nz = 0;
    {
        const float4* b4 = (const float4*)b3;
        for (int i = tid; i < DOUT/4; i += 256) {
            float4 v = __ldg(b4 + i);
            nz |= (v.x != 0.f) | (v.y != 0.f) | (v.z != 0.f) | (v.w != 0.f);
        }
    }
    nz = __syncthreads_or(nz);
    if (tid == 0 && bid == 0) g_bias_nz = nz;

    // ---- load s half-tile (coalesced) ----
    for (int idx = tid; idx < ROWS_PB*HH; idx += 256) {
        int r = idx >> 6, h = idx & 63;
        int bt = half*ROWS_PB + r;
        s_sm[idx] = state[((size_t)bt*NN + n)*HH + h];
    }

    // ---- load W3 into col-permuted smem: w_sm[k][side*128 + h*2 + m] ----
    for (int idx = tid*4; idx < 2*DOUT; idx += 1024) {
        float4 w4 = __ldg((const float4*)(W3 + idx));
        int m   = idx >> 13;
        int rem = idx & 8191;
        int kk  = rem >> 6;       // 0..127
        int h   = rem & 63;       // multiple of 4
        int kl  = kk & 63, side = kk >> 6;
        float* dstp = &w_sm[kl*256 + side*128 + h*2 + m];
        dstp[0] = w4.x; dstp[2] = w4.y; dstp[4] = w4.z; dstp[6] = w4.w;
    }
    if (nz) {   // bias planes: wz_sm[k][side*64 + h] = b3[kk*64+h]
        for (int idx = tid*4; idx < DOUT; idx += 1024) {
            float4 v = __ldg((const float4*)(b3 + idx));
            int kk = idx >> 6, h = idx & 63;
            int kl = kk & 63, side = kk >> 6;
            *(float4*)&wz_sm[kl*128 + side*64 + h] = v;
        }
    }

    // ---- per-edge hypernetwork (half==0 only; registers/shfl, no smem) ----
    if (half == 0) {
        int el = tid >> 4;           // edge 0..15
        int m  = tid & 15;           // hidden unit 0..15
        int e  = n*DEG + el;
        int se = __ldg(src + e);
        int de = __ldg(dst + e);
        float z = __ldg(b1 + m) + __ldg(dist + e) * __ldg(W1 + 2*FF*M1C + m);
        const float* fs = feature + se*FF;
        const float* fd = feature + de*FF;
        #pragma unroll 8
        for (int i = 0; i < FF; i++) {
            z = fmaf(__ldg(fs + i), __ldg(W1 + i*M1C + m), z);
            z = fmaf(__ldg(fd + i), __ldg(W1 + (FF+i)*M1C + m), z);
        }
        float h1 = sigmoidf_(z);
        float p0 = h1 * __ldg(W2 + m*M2C + 0);
        float p1 = h1 * __ldg(W2 + m*M2C + 1);
        #pragma unroll
        for (int mk = 1; mk < 16; mk <<= 1) {
            p0 += __shfl_xor_sync(0xFFFFFFFFu, p0, mk);
            p1 += __shfl_xor_sync(0xFFFFFFFFu, p1, mk);
        }
        if (m == 0) {
            g_c[e*2 + 0] = sigmoidf_(p0 + __ldg(b2 + 0));
            g_c[e*2 + 1] = sigmoidf_(p1 + __ldg(b2 + 1));
        }
    }
    __syncthreads();

    // ---- main GEMM: thread = (rg = tid>>5 rows rg+8r, cg = tid&31 cols cg*8..+7)
    int cg8 = (tid & 31) * 8;
    int rg  = tid >> 5;

    ull acc[6][4];
    #pragma unroll
    for (int r = 0; r < 6; r++)
        #pragma unroll
        for (int q = 0; q < 4; q++) acc[r][q] = 0ull;

    #pragma unroll 4
    for (int k = 0; k < HH; k++) {
        ulonglong2 w0 = *(const ulonglong2*)&w_sm[k*256 + cg8];
        ulonglong2 w1 = *(const ulonglong2*)&w_sm[k*256 + cg8 + 4];
        #pragma unroll
        for (int r = 0; r < 6; r++) {
            ull sd = dup2(s_sm[(rg + 8*r)*HH + k]);   // warp-uniform broadcast
            ffma2(acc[r][0], w0.x, sd);
            ffma2(acc[r][1], w0.y, sd);
            ffma2(acc[r][2], w1.x, sd);
            ffma2(acc[r][3], w1.y, sd);
        }
    }

    // ---- stores: cols cg8..cg8+7 = (h,m)-interleaved, 2 x STG.128 per row ----
    {
        int cg   = tid & 31;
        int sideB = (cg >= 16);
        float* outp = (sideB ? g_B : g_A) + (size_t)n*PLANE*2;
        int h0 = (cg & 15) * 4;
        #pragma unroll
        for (int r = 0; r < 6; r++) {
            int bt = half*ROWS_PB + rg + 8*r;
            float4 v0, v1;
            unpk2(acc[r][0], v0.x, v0.y);
            unpk2(acc[r][1], v0.z, v0.w);
            unpk2(acc[r][2], v1.x, v1.y);
            unpk2(acc[r][3], v1.z, v1.w);
            size_t base = ((size_t)bt*HH + h0) * 2;
            *(float4*)(outp + base)     = v0;
            *(float4*)(outp + base + 4) = v1;
        }
    }

    // ---- cold bias pass (b3 != 0): 128 cols, 6 rows x 4 cols per thread ----
    if (nz) {
        int cgb = tid & 31;          // 4 cols each over 128
        int c0b = cgb * 4;
        ull accz[6][2];
        #pragma unroll
        for (int r = 0; r < 6; r++) { accz[r][0] = 0ull; accz[r][1] = 0ull; }
        #pragma unroll 4
        for (int k = 0; k < HH; k++) {
            ulonglong2 wz = *(const ulonglong2*)&wz_sm[k*128 + c0b];
            #pragma unroll
            for (int r = 0; r < 6; r++) {
                ull sd = dup2(s_sm[(rg + 8*r)*HH + k]);
                ffma2(accz[r][0], wz.x, sd);
                ffma2(accz[r][1], wz.y, sd);
            }
        }
        int sideB = (cgb >= 16);
        int h0 = (cgb & 15) * 4;
        float* outp = (sideB ? g_Bz : g_Az) + (size_t)n*PLANE;
        #pragma unroll
        for (int r = 0; r < 6; r++) {
            int bt = half*ROWS_PB + rg + 8*r;
            float4 v;
            unpk2(accz[r][0], v.x, v.y);
            unpk2(accz[r][1], v.z, v.w);
            *(float4*)(outp + (size_t)bt*HH + h0) = v;
        }
    }
}

// ---------------------------------------------------------------------------
// K3: combine + single-pass softmax + aggregate. grid = N*6 bt-tiles.
// ---------------------------------------------------------------------------
__global__ void __launch_bounds__(256) k3_combine(
        const float* __restrict__ state,
        const float* __restrict__ gate,
        const int*   __restrict__ src,
        const int*   __restrict__ dst,
        float*       __restrict__ out) {
    int n    = blockIdx.x / 6;
    int tile = blockIdx.x % 6;

    __shared__ float c0s[DEG], c1s[DEG];
    __shared__ int   srcs[DEG];
    __shared__ int   dstn_s;
    int tid = threadIdx.x;
    if (tid < DEG) {
        int e = n*DEG + tid;
        srcs[tid] = src[e];
        c0s[tid]  = g_c[e*2 + 0];
        c1s[tid]  = g_c[e*2 + 1];
        if (tid == 0) dstn_s = dst[n*DEG];
    }
    int bias_nz = g_bias_nz;
    __syncthreads();

    int dstn = dstn_s;
    int h4   = (tid & 15) * 4;
    int bt   = tile*16 + (tid >> 4);
    size_t eoff = (size_t)bt*HH + h4;

    const float* yp = g_B + ((size_t)dstn*PLANE + eoff)*2;
    float4 ya = *(const float4*)(yp);
    float4 yb = *(const float4*)(yp + 4);

    float4 num = make_float4(0.f, 0.f, 0.f, 0.f);
    float4 den = make_float4(0.f, 0.f, 0.f, 0.f);

    if (!bias_nz) {
        #pragma unroll
        for (int j = 0; j < DEG; j++) {
            int sj = srcs[j];
            const float* xp = g_A + ((size_t)sj*PLANE + eoff)*2;
            float4 xa = *(const float4*)(xp);
            float4 xb = *(const float4*)(xp + 4);
            float4 s4 = *(const float4*)(state + ((size_t)bt*NN + sj)*HH + h4);
            float c0 = c0s[j], c1 = c1s[j];
            float4 a;
            a.x = fmaf(c0, xa.x + ya.x, c1 * (xa.y + ya.y));
            a.y = fmaf(c0, xa.z + ya.z, c1 * (xa.w + ya.w));
            a.z = fmaf(c0, xb.x + yb.x, c1 * (xb.y + yb.y));
            a.w = fmaf(c0, xb.z + yb.z, c1 * (xb.w + yb.w));
            a.x = fmaxf(a.x, 0.01f*a.x);
            a.y = fmaxf(a.y, 0.01f*a.y);
            a.z = fmaxf(a.z, 0.01f*a.z);
            a.w = fmaxf(a.w, 0.01f*a.w);
            float4 p;
            p.x = __expf(a.x); p.y = __expf(a.y);
            p.z = __expf(a.z); p.w = __expf(a.w);
            den.x += p.x; den.y += p.y; den.z += p.z; den.w += p.w;
            num.x = fmaf(p.x, s4.x, num.x);
            num.y = fmaf(p.y, s4.y, num.y);
            num.z = fmaf(p.z, s4.z, num.z);
            num.w = fmaf(p.w, s4.w, num.w);
        }
    } else {
        float4 y2 = *(const float4*)(g_Bz + (size_t)dstn*PLANE + eoff);
        #pragma unroll
        for (int j = 0; j < DEG; j++) {
            int sj = srcs[j];
            const float* xp = g_A + ((size_t)sj*PLANE + eoff)*2;
            float4 xa = *(const float4*)(xp);
            float4 xb = *(const float4*)(xp + 4);
            float4 x2 = *(const float4*)(g_Az + (size_t)sj*PLANE + eoff);
            float4 s4 = *(const float4*)(state + ((size_t)bt*NN + sj)*HH + h4);
            float c0 = c0s[j], c1 = c1s[j];
            float4 a;
            a.x = fmaf(c0, xa.x + ya.x, fmaf(c1, xa.y + ya.y, x2.x + y2.x));
            a.y = fmaf(c0, xa.z + ya.z, fmaf(c1, xa.w + ya.w, x2.y + y2.y));
            a.z = fmaf(c0, xb.x + yb.x, fmaf(c1, xb.y + yb.y, x2.z + y2.z));
            a.w = fmaf(c0, xb.z + yb.z, fmaf(c1, xb.w + yb.w, x2.w + y2.w));
            a.x = fmaxf(a.x, 0.01f*a.x);
            a.y = fmaxf(a.y, 0.01f*a.y);
            a.z = fmaxf(a.z, 0.01f*a.z);
            a.w = fmaxf(a.w, 0.01f*a.w);
            float4 p;
            p.x = __expf(a.x); p.y = __expf(a.y);
            p.z = __expf(a.z); p.w = __expf(a.w);
            den.x += p.x; den.y += p.y; den.z += p.z; den.w += p.w;
            num.x = fmaf(p.x, s4.x, num.x);
            num.y = fmaf(p.y, s4.y, num.y);
            num.z = fmaf(p.z, s4.z, num.z);
            num.w = fmaf(p.w, s4.w, num.w);
        }
    }

    float sg = 1.0f / (1.0f + __expf(-gate[0]));
    float4 o;
    o.x = fmaxf(num.x / den.x, 0.f) * sg;
    o.y = fmaxf(num.y / den.y, 0.f) * sg;
    o.z = fmaxf(num.z / den.z, 0.f) * sg;
    o.w = fmaxf(num.w / den.w, 0.f) * sg;
    *(float4*)(out + ((size_t)bt*NN + n)*HH + h4) = o;
}

// ---------------------------------------------------------------------------
extern "C" void kernel_launch(void* const* d_in, const int* in_sizes, int n_in,
                              void* d_out, int out_size) {
    const float* state   = (const float*)d_in[0];
    const float* feature = (const float*)d_in[1];
    const float* dist    = (const float*)d_in[2];
    const float* W1      = (const float*)d_in[3];
    const float* b1      = (const float*)d_in[4];
    const float* W2      = (const float*)d_in[5];
    const float* b2      = (const float*)d_in[6];
    const float* W3      = (const float*)d_in[7];
    const float* b3      = (const float*)d_in[8];
    const float* gate    = (const float*)d_in[9];
    const int*   src     = (const int*)d_in[10];
    const int*   dst     = (const int*)d_in[11];
    float* out = (float*)d_out;

    // Opt into >48KB dynamic smem. First (eager) call sets it before graph
    // capture; the redundant set during capture is harmless (return ignored).
    (void)cudaFuncSetAttribute((const void*)k2_precompute,
                               cudaFuncAttributeMaxDynamicSharedMemorySize,
                               K2_SMEM_BYTES);

    k2_precompute<<<NN*2, 256, K2_SMEM_BYTES>>>(state, feature, dist, W1, b1,
                                                W2, b2, W3, b3, src, dst);
    k3_combine<<<NN*6, 256>>>(state, gate, src, dst, out);
}

// round 8
// speedup vs baseline: 1.2670x; 1.2670x over previous
#include <cuda_runtime.h>
#include <math.h>

#define NN   500
#define DEG  16
#define BB   8
#define TT   12
#define HH   64
#define FF   32
#define EE   (NN*DEG)      // 8000
#define BT   (BB*TT)       // 96
#define M1C  16
#define M2C  2
#define DOUT (2*HH*HH)     // 8192
#define PLANE (BT*HH)      // 6144
#define SPITCH 68

// Static scratch (allocation-free)
__device__ int   g_bias_nz;                  // b3 != 0 anywhere?
__device__ float g_c[EE*2];                  // per-edge (c0,c1)
__device__ float g_A[(size_t)NN*PLANE*2];    // src-side planes interleaved (x0,x1)
__device__ float g_B[(size_t)NN*PLANE*2];    // dst-side planes interleaved (y0,y1)
__device__ float g_Az[(size_t)NN*PLANE];     // src bias plane (only if b3 != 0)
__device__ float g_Bz[(size_t)NN*PLANE];     // dst bias plane

typedef unsigned long long ull;

__device__ __forceinline__ ull dup2(float x) {
    ull r;
    asm("mov.b64 %0, {%1, %1};" : "=l"(r) : "r"(__float_as_uint(x)));
    return r;
}
__device__ __forceinline__ void ffma2(ull& d, ull a, ull b) {
    asm("fma.rn.f32x2 %0, %1, %2, %3;" : "=l"(d) : "l"(a), "l"(b), "l"(d));
}
__device__ __forceinline__ void unpk2(ull v, float& lo, float& hi) {
    unsigned ulo, uhi;
    asm("mov.b64 {%0, %1}, %2;" : "=r"(ulo), "=r"(uhi) : "l"(v));
    lo = __uint_as_float(ulo); hi = __uint_as_float(uhi);
}
__device__ __forceinline__ float sigmoidf_(float x) {
    return __fdividef(1.0f, 1.0f + __expf(-x));
}

// ---------------------------------------------------------------------------
// K2: per-(node, side) projections. grid = 2N, block = 256.  (round-6 version:
// at the measured fp32-pipe floor ~51us)
// ---------------------------------------------------------------------------
__global__ void __launch_bounds__(256) k2_precompute(
        const float* __restrict__ state,
        const float* __restrict__ feature,
        const float* __restrict__ dist,
        const float* __restrict__ W1,
        const float* __restrict__ b1,
        const float* __restrict__ W2,
        const float* __restrict__ b2,
        const float* __restrict__ W3,
        const float* __restrict__ b3,
        const int*   __restrict__ src,
        const int*   __restrict__ dst) {
    int bid  = blockIdx.x;
    int n    = bid >> 1;
    int side = bid & 1;
    __shared__ float s_sm[BT*SPITCH];   // 26112 B
    __shared__ float w_sm[HH*HH];       // 16384 B
    int tid = threadIdx.x;

    // bias-nonzero scan (b3 = 32KB, L2-resident; hidden under the FMA phase)
    int nz = 0;
    {
        const float4* b4 = (const float4*)b3;
        for (int i = tid; i < DOUT/4; i += 256) {
            float4 v = __ldg(b4 + i);
            nz |= (v.x != 0.f) | (v.y != 0.f) | (v.z != 0.f) | (v.w != 0.f);
        }
    }
    nz = __syncthreads_or(nz);
    if (tid == 0 && bid == 0) g_bias_nz = nz;
    int nm = nz ? 3 : 2;

    // load s[n] (node-major view of state[B,T,N,H]) into padded smem
    for (int idx = tid; idx < BT*HH; idx += 256) {
        int bt = idx >> 6, h = idx & 63;
        s_sm[bt*SPITCH + h] = state[((size_t)bt*NN + n)*HH + h];
    }

    // side 0: per-edge hypernetwork for segment n (thread = (edge, unit))
    if (side == 0) {
        int el = tid >> 4;           // edge 0..15
        int m  = tid & 15;           // hidden unit 0..15
        int e  = n*DEG + el;
        int se = __ldg(src + e);
        int de = __ldg(dst + e);
        float z = __ldg(b1 + m) + __ldg(dist + e) * __ldg(W1 + 2*FF*M1C + m);
        const float* fs = feature + se*FF;
        const float* fd = feature + de*FF;
        #pragma unroll 8
        for (int i = 0; i < FF; i++) {
            z = fmaf(__ldg(fs + i), __ldg(W1 + i*M1C + m), z);
            z = fmaf(__ldg(fd + i), __ldg(W1 + (FF+i)*M1C + m), z);
        }
        float h1 = sigmoidf_(z);
        float p0 = h1 * __ldg(W2 + m*M2C + 0);
        float p1 = h1 * __ldg(W2 + m*M2C + 1);
        #pragma unroll
        for (int mk = 1; mk < 16; mk <<= 1) {
            p0 += __shfl_xor_sync(0xFFFFFFFFu, p0, mk);
            p1 += __shfl_xor_sync(0xFFFFFFFFu, p1, mk);
        }
        if (m == 0) {
            g_c[e*2 + 0] = sigmoidf_(p0 + __ldg(b2 + 0));
            g_c[e*2 + 1] = sigmoidf_(p1 + __ldg(b2 + 1));
        }
    }

    int c4 = (tid & 15) * 4;     // output cols c4..c4+3
    int ty = tid >> 4;           // rows ty, ty+16, ..., ty+80
    float o0[6][4];

    for (int mi = 0; mi < nm; mi++) {
        __syncthreads();
        {
            const float* wp = (mi == 0) ? W3 : (mi == 1) ? (W3 + DOUT) : b3;
            int base = side ? HH*HH : 0;
            for (int idx = tid; idx < HH*HH; idx += 256)
                w_sm[idx] = wp[base + idx];
        }
        __syncthreads();

        ull acc[6][2];
        #pragma unroll
        for (int r = 0; r < 6; r++) { acc[r][0] = 0ull; acc[r][1] = 0ull; }

        #pragma unroll 4
        for (int k4 = 0; k4 < 16; k4++) {
            float4 sv[6];
            #pragma unroll
            for (int r = 0; r < 6; r++)
                sv[r] = *(const float4*)&s_sm[(ty + 16*r)*SPITCH + k4*4];
            #pragma unroll
            for (int kk = 0; kk < 4; kk++) {
                int k = k4*4 + kk;
                ulonglong2 wp2 = *(const ulonglong2*)&w_sm[k*HH + c4];
                #pragma unroll
                for (int r = 0; r < 6; r++) {
                    float sval = (kk == 0) ? sv[r].x : (kk == 1) ? sv[r].y
                               : (kk == 2) ? sv[r].z : sv[r].w;
                    ull sd = dup2(sval);
                    ffma2(acc[r][0], wp2.x, sd);
                    ffma2(acc[r][1], wp2.y, sd);
                }
            }
        }

        if (mi == 0) {
            #pragma unroll
            for (int r = 0; r < 6; r++) {
                unpk2(acc[r][0], o0[r][0], o0[r][1]);
                unpk2(acc[r][1], o0[r][2], o0[r][3]);
            }
        } else if (mi == 1) {
            float* outp = (side ? g_B : g_A) + (size_t)n*PLANE*2;
            #pragma unroll
            for (int r = 0; r < 6; r++) {
                int row = ty + 16*r;
                float m1v[4];
                unpk2(acc[r][0], m1v[0], m1v[1]);
                unpk2(acc[r][1], m1v[2], m1v[3]);
                size_t base = ((size_t)row*HH + c4) * 2;
                *(float4*)(outp + base)     = make_float4(o0[r][0], m1v[0], o0[r][1], m1v[1]);
                *(float4*)(outp + base + 4) = make_float4(o0[r][2], m1v[2], o0[r][3], m1v[3]);
            }
        } else {
            float* outp = (side ? g_Bz : g_Az) + (size_t)n*PLANE;
            #pragma unroll
            for (int r = 0; r < 6; r++) {
                int row = ty + 16*r;
                float zv[4];
                unpk2(acc[r][0], zv[0], zv[1]);
                unpk2(acc[r][1], zv[2], zv[3]);
                *(float4*)(outp + row*HH + c4) = make_float4(zv[0], zv[1], zv[2], zv[3]);
            }
        }
    }
}

// ---------------------------------------------------------------------------
// K3: combine + single-pass softmax + aggregate. grid = N*6 bt-tiles.
// __launch_bounds__(256,4): cap regs at 64 -> 4 blocks/SM (occ 50%).
// ---------------------------------------------------------------------------
__global__ void __launch_bounds__(256, 4) k3_combine(
        const float* __restrict__ state,
        const float* __restrict__ gate,
        const int*   __restrict__ src,
        const int*   __restrict__ dst,
        float*       __restrict__ out) {
    int n    = blockIdx.x / 6;
    int tile = blockIdx.x % 6;

    __shared__ float c0s[DEG], c1s[DEG];
    __shared__ int   srcs[DEG];
    __shared__ int   dstn_s;
    int tid = threadIdx.x;
    if (tid < DEG) {
        int e = n*DEG + tid;
        srcs[tid] = src[e];
        c0s[tid]  = g_c[e*2 + 0];
        c1s[tid]  = g_c[e*2 + 1];
        if (tid == 0) dstn_s = dst[n*DEG];
    }
    int bias_nz = g_bias_nz;
    __syncthreads();

    int dstn = dstn_s;
    int h4   = (tid & 15) * 4;
    int bt   = tile*16 + (tid >> 4);
    size_t eoff = (size_t)bt*HH + h4;

    const float* yp = g_B + ((size_t)dstn*PLANE + eoff)*2;
    float4 ya = *(const float4*)(yp);
    float4 yb = *(const float4*)(yp + 4);

    float4 num = make_float4(0.f, 0.f, 0.f, 0.f);
    float4 den = make_float4(0.f, 0.f, 0.f, 0.f);

    if (!bias_nz) {
        #pragma unroll
        for (int j = 0; j < DEG; j++) {
            int sj = srcs[j];
            const float* xp = g_A + ((size_t)sj*PLANE + eoff)*2;
            float4 xa = *(const float4*)(xp);
            float4 xb = *(const float4*)(xp + 4);
            float4 s4 = *(const float4*)(state + ((size_t)bt*NN + sj)*HH + h4);
            float c0 = c0s[j], c1 = c1s[j];
            float4 a;
            a.x = fmaf(c0, xa.x + ya.x, c1 * (xa.y + ya.y));
            a.y = fmaf(c0, xa.z + ya.z, c1 * (xa.w + ya.w));
            a.z = fmaf(c0, xb.x + yb.x, c1 * (xb.y + yb.y));
            a.w = fmaf(c0, xb.z + yb.z, c1 * (xb.w + yb.w));
            a.x = fmaxf(a.x, 0.01f*a.x);
            a.y = fmaxf(a.y, 0.01f*a.y);
            a.z = fmaxf(a.z, 0.01f*a.z);
            a.w = fmaxf(a.w, 0.01f*a.w);
            float4 p;
            p.x = __expf(a.x); p.y = __expf(a.y);
            p.z = __expf(a.z); p.w = __expf(a.w);
            den.x += p.x; den.y += p.y; den.z += p.z; den.w += p.w;
            num.x = fmaf(p.x, s4.x, num.x);
            num.y = fmaf(p.y, s4.y, num.y);
            num.z = fmaf(p.z, s4.z, num.z);
            num.w = fmaf(p.w, s4.w, num.w);
        }
    } else {
        float4 y2 = *(const float4*)(g_Bz + (size_t)dstn*PLANE + eoff);
        #pragma unroll
        for (int j = 0; j < DEG; j++) {
            int sj = srcs[j];
            const float* xp = g_A + ((size_t)sj*PLANE + eoff)*2;
            float4 xa = *(const float4*)(xp);
            float4 xb = *(const float4*)(xp + 4);
            float4 x2 = *(const float4*)(g_Az + (size_t)sj*PLANE + eoff);
            float4 s4 = *(const float4*)(state + ((size_t)bt*NN + sj)*HH + h4);
            float c0 = c0s[j], c1 = c1s[j];
            float4 a;
            a.x = fmaf(c0, xa.x + ya.x, fmaf(c1, xa.y + ya.y, x2.x + y2.x));
            a.y = fmaf(c0, xa.z + ya.z, fmaf(c1, xa.w + ya.w, x2.y + y2.y));
            a.z = fmaf(c0, xb.x + yb.x, fmaf(c1, xb.y + yb.y, x2.z + y2.z));
            a.w = fmaf(c0, xb.z + yb.z, fmaf(c1, xb.w + yb.w, x2.w + y2.w));
            a.x = fmaxf(a.x, 0.01f*a.x);
            a.y = fmaxf(a.y, 0.01f*a.y);
            a.z = fmaxf(a.z, 0.01f*a.z);
            a.w = fmaxf(a.w, 0.01f*a.w);
            float4 p;
            p.x = __expf(a.x); p.y = __expf(a.y);
            p.z = __expf(a.z); p.w = __expf(a.w);
            den.x += p.x; den.y += p.y; den.z += p.z; den.w += p.w;
            num.x = fmaf(p.x, s4.x, num.x);
            num.y = fmaf(p.y, s4.y, num.y);
            num.z = fmaf(p.z, s4.z, num.z);
            num.w = fmaf(p.w, s4.w, num.w);
        }
    }

    float sg = sigmoidf_(gate[0]);
    float4 o;
    o.x = fmaxf(__fdividef(num.x, den.x), 0.f) * sg;
    o.y = fmaxf(__fdividef(num.y, den.y), 0.f) * sg;
    o.z = fmaxf(__fdividef(num.z, den.z), 0.f) * sg;
    o.w = fmaxf(__fdividef(num.w, den.w), 0.f) * sg;
    *(float4*)(out + ((size_t)bt*NN + n)*HH + h4) = o;
}

// ---------------------------------------------------------------------------
extern "C" void kernel_launch(void* const* d_in, const int* in_sizes, int n_in,
                              void* d_out, int out_size) {
    const float* state   = (const float*)d_in[0];
    const float* feature = (const float*)d_in[1];
    const float* dist    = (const float*)d_in[2];
    const float* W1      = (const float*)d_in[3];
    const float* b1      = (const float*)d_in[4];
    const float* W2      = (const float*)d_in[5];
    const float* b2      = (const float*)d_in[6];
    const float* W3      = (const float*)d_in[7];
    const float* b3      = (const float*)d_in[8];
    const float* gate    = (const float*)d_in[9];
    const int*   src     = (const int*)d_in[10];
    const int*   dst     = (const int*)d_in[11];
    float* out = (float*)d_out;

    k2_precompute<<<NN*2, 256>>>(state, feature, dist, W1, b1, W2, b2,
                                 W3, b3, src, dst);
    k3_combine<<<NN*6, 256>>>(state, gate, src, dst, out);
}

// round 9
// speedup vs baseline: 1.3544x; 1.0690x over previous
#include <cuda_runtime.h>
#include <math.h>

#define NN   500
#define DEG  16
#define BB   8
#define TT   12
#define HH   64
#define FF   32
#define EE   (NN*DEG)      // 8000
#define BT   (BB*TT)       // 96
#define M1C  16
#define M2C  2
#define DOUT (2*HH*HH)     // 8192
#define PLANE (BT*HH)      // 6144
#define SPITCH 68

// Static scratch (allocation-free)
__device__ int   g_bias_nz;                  // b3 != 0 anywhere?
__device__ float g_c[EE*2];                  // per-edge (c0,c1)
__device__ float g_A[(size_t)NN*PLANE*2];    // src-side planes: [n][m][bt][h] (m=0,1)
__device__ float g_B[(size_t)NN*PLANE*2];    // dst-side planes: [n][m][bt][h]
__device__ float g_Az[(size_t)NN*PLANE];     // src bias plane (only if b3 != 0)
__device__ float g_Bz[(size_t)NN*PLANE];     // dst bias plane

typedef unsigned long long ull;

__device__ __forceinline__ ull dup2(float x) {
    ull r;
    asm("mov.b64 %0, {%1, %1};" : "=l"(r) : "r"(__float_as_uint(x)));
    return r;
}
__device__ __forceinline__ void ffma2(ull& d, ull a, ull b) {
    asm("fma.rn.f32x2 %0, %1, %2, %3;" : "=l"(d) : "l"(a), "l"(b), "l"(d));
}
__device__ __forceinline__ void unpk2(ull v, float& lo, float& hi) {
    unsigned ulo, uhi;
    asm("mov.b64 {%0, %1}, %2;" : "=r"(ulo), "=r"(uhi) : "l"(v));
    lo = __uint_as_float(ulo); hi = __uint_as_float(uhi);
}
__device__ __forceinline__ float sigmoidf_(float x) {
    return __fdividef(1.0f, 1.0f + __expf(-x));
}

// ---------------------------------------------------------------------------
// K2: per-(node, side) projections. grid = 2N, block = 256.
// ---------------------------------------------------------------------------
__global__ void __launch_bounds__(256) k2_precompute(
        const float* __restrict__ state,
        const float* __restrict__ feature,
        const float* __restrict__ dist,
        const float* __restrict__ W1,
        const float* __restrict__ b1,
        const float* __restrict__ W2,
        const float* __restrict__ b2,
        const float* __restrict__ W3,
        const float* __restrict__ b3,
        const int*   __restrict__ src,
        const int*   __restrict__ dst) {
    int bid  = blockIdx.x;
    int n    = bid >> 1;
    int side = bid & 1;
    __shared__ float s_sm[BT*SPITCH];   // 26112 B
    __shared__ float w_sm[HH*HH];       // 16384 B
    int tid = threadIdx.x;

    // bias-nonzero scan (b3 = 32KB, L2-resident; hidden under the FMA phase)
    int nz = 0;
    {
        const float4* b4 = (const float4*)b3;
        for (int i = tid; i < DOUT/4; i += 256) {
            float4 v = __ldg(b4 + i);
            nz |= (v.x != 0.f) | (v.y != 0.f) | (v.z != 0.f) | (v.w != 0.f);
        }
    }
    nz = __syncthreads_or(nz);
    if (tid == 0 && bid == 0) g_bias_nz = nz;
    int nm = nz ? 3 : 2;

    // load s[n] (node-major view of state[B,T,N,H]) into padded smem
    for (int idx = tid; idx < BT*HH; idx += 256) {
        int bt = idx >> 6, h = idx & 63;
        s_sm[bt*SPITCH + h] = state[((size_t)bt*NN + n)*HH + h];
    }

    // side 0: per-edge hypernetwork for segment n (thread = (edge, unit))
    if (side == 0) {
        int el = tid >> 4;           // edge 0..15
        int m  = tid & 15;           // hidden unit 0..15
        int e  = n*DEG + el;
        int se = __ldg(src + e);
        int de = __ldg(dst + e);
        float z = __ldg(b1 + m) + __ldg(dist + e) * __ldg(W1 + 2*FF*M1C + m);
        const float* fs = feature + se*FF;
        const float* fd = feature + de*FF;
        #pragma unroll 8
        for (int i = 0; i < FF; i++) {
            z = fmaf(__ldg(fs + i), __ldg(W1 + i*M1C + m), z);
            z = fmaf(__ldg(fd + i), __ldg(W1 + (FF+i)*M1C + m), z);
        }
        float h1 = sigmoidf_(z);
        float p0 = h1 * __ldg(W2 + m*M2C + 0);
        float p1 = h1 * __ldg(W2 + m*M2C + 1);
        #pragma unroll
        for (int mk = 1; mk < 16; mk <<= 1) {
            p0 += __shfl_xor_sync(0xFFFFFFFFu, p0, mk);
            p1 += __shfl_xor_sync(0xFFFFFFFFu, p1, mk);
        }
        if (m == 0) {
            g_c[e*2 + 0] = sigmoidf_(p0 + __ldg(b2 + 0));
            g_c[e*2 + 1] = sigmoidf_(p1 + __ldg(b2 + 1));
        }
    }

    int c4 = (tid & 15) * 4;     // output cols c4..c4+3
    int ty = tid >> 4;           // rows ty, ty+16, ..., ty+80
    float o0[6][4];

    for (int mi = 0; mi < nm; mi++) {
        __syncthreads();
        {
            const float* wp = (mi == 0) ? W3 : (mi == 1) ? (W3 + DOUT) : b3;
            int base = side ? HH*HH : 0;
            for (int idx = tid; idx < HH*HH; idx += 256)
                w_sm[idx] = wp[base + idx];
        }
        __syncthreads();

        ull acc[6][2];
        #pragma unroll
        for (int r = 0; r < 6; r++) { acc[r][0] = 0ull; acc[r][1] = 0ull; }

        #pragma unroll 4
        for (int k4 = 0; k4 < 16; k4++) {
            float4 sv[6];
            #pragma unroll
            for (int r = 0; r < 6; r++)
                sv[r] = *(const float4*)&s_sm[(ty + 16*r)*SPITCH + k4*4];
            #pragma unroll
            for (int kk = 0; kk < 4; kk++) {
                int k = k4*4 + kk;
                ulonglong2 wp2 = *(const ulonglong2*)&w_sm[k*HH + c4];
                #pragma unroll
                for (int r = 0; r < 6; r++) {
                    float sval = (kk == 0) ? sv[r].x : (kk == 1) ? sv[r].y
                               : (kk == 2) ? sv[r].z : sv[r].w;
                    ull sd = dup2(sval);
                    ffma2(acc[r][0], wp2.x, sd);
                    ffma2(acc[r][1], wp2.y, sd);
                }
            }
        }

        if (mi == 0) {
            #pragma unroll
            for (int r = 0; r < 6; r++) {
                unpk2(acc[r][0], o0[r][0], o0[r][1]);
                unpk2(acc[r][1], o0[r][2], o0[r][3]);
            }
        } else if (mi == 1) {
            // plane-separated stores: plane0 = m0 (o0), plane1 = m1 (acc)
            float* outp = (side ? g_B : g_A) + (size_t)n*PLANE*2;
            #pragma unroll
            for (int r = 0; r < 6; r++) {
                int row = ty + 16*r;
                float m1v[4];
                unpk2(acc[r][0], m1v[0], m1v[1]);
                unpk2(acc[r][1], m1v[2], m1v[3]);
                size_t base = (size_t)row*HH + c4;
                *(float4*)(outp + base)         = make_float4(o0[r][0], o0[r][1], o0[r][2], o0[r][3]);
                *(float4*)(outp + PLANE + base) = make_float4(m1v[0], m1v[1], m1v[2], m1v[3]);
            }
        } else {
            float* outp = (side ? g_Bz : g_Az) + (size_t)n*PLANE;
            #pragma unroll
            for (int r = 0; r < 6; r++) {
                int row = ty + 16*r;
                float zv[4];
                unpk2(acc[r][0], zv[0], zv[1]);
                unpk2(acc[r][1], zv[2], zv[3]);
                *(float4*)(outp + row*HH + c4) = make_float4(zv[0], zv[1], zv[2], zv[3]);
            }
        }
    }
}

// ---------------------------------------------------------------------------
// K3: combine + single-pass softmax + aggregate. grid = N*6 bt-tiles.
// Plane-separated loads: every stream lane-contiguous (min L1 wavefronts).
// ---------------------------------------------------------------------------
__global__ void __launch_bounds__(256, 4) k3_combine(
        const float* __restrict__ state,
        const float* __restrict__ gate,
        const int*   __restrict__ src,
        const int*   __restrict__ dst,
        float*       __restrict__ out) {
    int n    = blockIdx.x / 6;
    int tile = blockIdx.x % 6;

    __shared__ float c0s[DEG], c1s[DEG];
    __shared__ int   srcs[DEG];
    __shared__ int   dstn_s;
    int tid = threadIdx.x;
    if (tid < DEG) {
        int e = n*DEG + tid;
        srcs[tid] = src[e];
        c0s[tid]  = g_c[e*2 + 0];
        c1s[tid]  = g_c[e*2 + 1];
        if (tid == 0) dstn_s = dst[n*DEG];
    }
    int bias_nz = g_bias_nz;
    __syncthreads();

    int dstn = dstn_s;
    int h4   = (tid & 15) * 4;
    int bt   = tile*16 + (tid >> 4);
    size_t eoff = (size_t)bt*HH + h4;

    const float* yp = g_B + (size_t)dstn*PLANE*2 + eoff;
    float4 y0 = *(const float4*)(yp);
    float4 y1 = *(const float4*)(yp + PLANE);

    float4 num = make_float4(0.f, 0.f, 0.f, 0.f);
    float4 den = make_float4(0.f, 0.f, 0.f, 0.f);

    if (!bias_nz) {
        #pragma unroll
        for (int j = 0; j < DEG; j++) {
            int sj = srcs[j];
            const float* xp = g_A + (size_t)sj*PLANE*2 + eoff;
            float4 x0 = *(const float4*)(xp);
            float4 x1 = *(const float4*)(xp + PLANE);
            float4 s4 = *(const float4*)(state + ((size_t)bt*NN + sj)*HH + h4);
            float c0 = c0s[j], c1 = c1s[j];
            float4 a;
            a.x = fmaf(c0, x0.x + y0.x, c1 * (x1.x + y1.x));
            a.y = fmaf(c0, x0.y + y0.y, c1 * (x1.y + y1.y));
            a.z = fmaf(c0, x0.z + y0.z, c1 * (x1.z + y1.z));
            a.w = fmaf(c0, x0.w + y0.w, c1 * (x1.w + y1.w));
            a.x = fmaxf(a.x, 0.01f*a.x);
            a.y = fmaxf(a.y, 0.01f*a.y);
            a.z = fmaxf(a.z, 0.01f*a.z);
            a.w = fmaxf(a.w, 0.01f*a.w);
            float4 p;
            p.x = __expf(a.x); p.y = __expf(a.y);
            p.z = __expf(a.z); p.w = __expf(a.w);
            den.x += p.x; den.y += p.y; den.z += p.z; den.w += p.w;
            num.x = fmaf(p.x, s4.x, num.x);
            num.y = fmaf(p.y, s4.y, num.y);
            num.z = fmaf(p.z, s4.z, num.z);
            num.w = fmaf(p.w, s4.w, num.w);
        }
    } else {
        float4 y2 = *(const float4*)(g_Bz + (size_t)dstn*PLANE + eoff);
        #pragma unroll
        for (int j = 0; j < DEG; j++) {
            int sj = srcs[j];
            const float* xp = g_A + (size_t)sj*PLANE*2 + eoff;
            float4 x0 = *(const float4*)(xp);
            float4 x1 = *(const float4*)(xp + PLANE);
            float4 x2 = *(const float4*)(g_Az + (size_t)sj*PLANE + eoff);
            float4 s4 = *(const float4*)(state + ((size_t)bt*NN + sj)*HH + h4);
            float c0 = c0s[j], c1 = c1s[j];
            float4 a;
            a.x = fmaf(c0, x0.x + y0.x, fmaf(c1, x1.x + y1.x, x2.x + y2.x));
            a.y = fmaf(c0, x0.y + y0.y, fmaf(c1, x1.y + y1.y, x2.y + y2.y));
            a.z = fmaf(c0, x0.z + y0.z, fmaf(c1, x1.z + y1.z, x2.z + y2.z));
            a.w = fmaf(c0, x0.w + y0.w, fmaf(c1, x1.w + y1.w, x2.w + y2.w));
            a.x = fmaxf(a.x, 0.01f*a.x);
            a.y = fmaxf(a.y, 0.01f*a.y);
            a.z = fmaxf(a.z, 0.01f*a.z);
            a.w = fmaxf(a.w, 0.01f*a.w);
            float4 p;
            p.x = __expf(a.x); p.y = __expf(a.y);
            p.z = __expf(a.z); p.w = __expf(a.w);
            den.x += p.x; den.y += p.y; den.z += p.z; den.w += p.w;
            num.x = fmaf(p.x, s4.x, num.x);
            num.y = fmaf(p.y, s4.y, num.y);
            num.z = fmaf(p.z, s4.z, num.z);
            num.w = fmaf(p.w, s4.w, num.w);
        }
    }

    float sg = sigmoidf_(gate[0]);
    float4 o;
    o.x = fmaxf(__fdividef(num.x, den.x), 0.f) * sg;
    o.y = fmaxf(__fdividef(num.y, den.y), 0.f) * sg;
    o.z = fmaxf(__fdividef(num.z, den.z), 0.f) * sg;
    o.w = fmaxf(__fdividef(num.w, den.w), 0.f) * sg;
    *(float4*)(out + ((size_t)bt*NN + n)*HH + h4) = o;
}

// ---------------------------------------------------------------------------
extern "C" void kernel_launch(void* const* d_in, const int* in_sizes, int n_in,
                              void* d_out, int out_size) {
    const float* state   = (const float*)d_in[0];
    const float* feature = (const float*)d_in[1];
    const float* dist    = (const float*)d_in[2];
    const float* W1      = (const float*)d_in[3];
    const float* b1      = (const float*)d_in[4];
    const float* W2      = (const float*)d_in[5];
    const float* b2      = (const float*)d_in[6];
    const float* W3      = (const float*)d_in[7];
    const float* b3      = (const float*)d_in[8];
    const float* gate    = (const float*)d_in[9];
    const int*   src     = (const int*)d_in[10];
    const int*   dst     = (const int*)d_in[11];
    float* out = (float*)d_out;

    k2_precompute<<<NN*2, 256>>>(state, feature, dist, W1, b1, W2, b2,
                                 W3, b3, src, dst);
    k3_combine<<<NN*6, 256>>>(state, gate, src, dst, out);
}